// round 15
// baseline (speedup 1.0000x reference)
#include <cuda_runtime.h>
#include <cstdint>

// Problem constants
#define CCH 64      // channels
#define NI  16      // irreps
#define NK2 120
#define NK1 8
#define NK0 4

#define NPAIR 136        // #(x<=y) pairs
#define RUN_TOTAL 888    // sum over pairs of padded run lengths Lp(y)=((16-y)+1)&~1
#define TAB_ULL   (RUN_TOTAL + NPAIR + NI)   // 1040 ull per channel
#define TILE_ATOMS 512   // atoms per work item (2 per thread, 256 threads)

typedef unsigned long long ull;

// Scratch (__device__ globals; no allocation)
__device__ ull g_tab[CCH * TAB_ULL];   // per-channel packed dup'd tables:
                                       //   [0,888)     At (cubic)
                                       //   [888,1024)  c1s
                                       //   [1024,1040) c0s

__device__ __forceinline__ ull pack2(float lo, float hi) {
    ull r; asm("mov.b64 %0,{%1,%2};" : "=l"(r) : "f"(lo), "f"(hi)); return r;
}
__device__ __forceinline__ ull dup2(float v) { return pack2(v, v); }
__device__ __forceinline__ void unpack2(ull v, float& lo, float& hi) {
    asm("mov.b64 {%0,%1},%2;" : "=f"(lo), "=f"(hi) : "l"(v));
}
__device__ __forceinline__ ull fma2(ull a, ull b, ull c) {
    ull d; asm("fma.rn.f32x2 %0,%1,%2,%3;" : "=l"(d) : "l"(a), "l"(b), "l"(c)); return d;
}

// Sum of U2 over DISTINCT index-permutations of the multiset {x,y,i}, at basis k.
__device__ __forceinline__ float sym_sum_U2(const float* __restrict__ U2,
                                            int x, int y, int i, int k) {
    int ta[6] = {x, x, y, y, i, i};
    int tb[6] = {y, i, x, i, x, y};
    int tc[6] = {i, y, i, x, y, x};
    int seen[6]; int ns = 0;
    float v = 0.f;
    #pragma unroll
    for (int q = 0; q < 6; q++) {
        int code = (ta[q] << 8) | (tb[q] << 4) | tc[q];
        bool dup = false;
        for (int s = 0; s < ns; s++) if (seen[s] == code) dup = true;
        if (!dup) {
            seen[ns++] = code;
            v += U2[(((ta[q] * NI + tb[q]) * NI) + tc[q]) * NK2 + k];
        }
    }
    return v;
}

// decode padded-run row -> (x, y, j-within-run)
__device__ __forceinline__ void decode_row(int row, int& x, int& y, int& i) {
    int yy = 0, base = 0, Lp = 0;
    for (;;) {
        Lp = ((NI - yy) + 1) & ~1;
        int sz = (yy + 1) * Lp;
        if (row < base + sz) break;
        base += sz; yy++;
    }
    int rem = row - base;
    x = rem / Lp;
    int j = rem - x * Lp;
    y = yy;
    i = (NI - Lp) + j;
}

// ---------------------------------------------------------------------------
// Fused prep kernel: symmetrize + weight-contract directly into g_tab.
// Blocks 0..55: compute 16 Usym rows in smem (sym gathers), then GEMM vs w2.
// Block 56: c1s (U1 symmetrized inline) + c0s.
// ---------------------------------------------------------------------------
__global__ __launch_bounds__(256)
void prep_kernel(const float* __restrict__ U2,
                 const float* __restrict__ U1,
                 const float* __restrict__ U0,
                 const float* __restrict__ w2,
                 const float* __restrict__ w1,
                 const float* __restrict__ w0) {
    const int bid = blockIdx.x, tid = threadIdx.x;
    if (bid < 56) {
        __shared__ float sW[NK2 * CCH];      // 30 KB
        __shared__ float sU[16 * NK2];       // 7.5 KB
        const int r0 = bid * 16;
        for (int i = tid; i < NK2 * CCH; i += 256) sW[i] = w2[i];
        // compute the 16 Usym rows directly (one thread per (row,k) output)
        for (int e = tid; e < 16 * NK2; e += 256) {
            const int rr = r0 + e / NK2;
            const int k  = e % NK2;
            float v = 0.f;
            if (rr < RUN_TOTAL) {
                int x, y, i;
                decode_row(rr, x, y, i);
                if (i >= y) v = sym_sum_U2(U2, x, y, i, k);
            }
            sU[e] = v;
        }
        __syncthreads();
        const int c = tid & 63;
        const int tr = tid >> 6;             // 0..3
        float acc[4] = {0.f, 0.f, 0.f, 0.f};
        #pragma unroll 4
        for (int k = 0; k < NK2; k++) {
            float wv = sW[k * CCH + c];
            #pragma unroll
            for (int q = 0; q < 4; q++)
                acc[q] += sU[(tr + 4 * q) * NK2 + k] * wv;
        }
        #pragma unroll
        for (int q = 0; q < 4; q++) {
            int row = r0 + tr + 4 * q;
            if (row < RUN_TOTAL) g_tab[(size_t)c * TAB_ULL + row] = dup2(acc[q]);
        }
    } else {
        // c1s: symmetrized U1 contracted with w1, inline
        for (int idx = tid; idx < CCH * NPAIR; idx += 256) {
            int c = idx & 63, p = idx >> 6;
            int y = 0;
            while ((y + 1) * (y + 2) / 2 <= p) y++;
            int x = p - y * (y + 1) / 2;
            float s = 0.f;
            #pragma unroll
            for (int k = 0; k < NK1; k++) {
                float u = U1[(x * NI + y) * NK1 + k];
                if (x != y) u += U1[(y * NI + x) * NK1 + k];
                s += u * w1[k * CCH + c];
            }
            g_tab[(size_t)c * TAB_ULL + RUN_TOTAL + p] = dup2(s);
        }
        for (int idx = tid; idx < CCH * NI; idx += 256) {
            int c = idx & 63, x = idx >> 6;
            float s = 0.f;
            #pragma unroll
            for (int k = 0; k < NK0; k++) s += U0[x * NK0 + k] * w0[k * CCH + c];
            g_tab[(size_t)c * TAB_ULL + RUN_TOTAL + NPAIR + x] = dup2(s);
        }
    }
}

// ---------------------------------------------------------------------------
// Contract kernel: STATIC channel-major chunking, 456 CTAs (152 SM x 3),
// 256 threads, TWO atoms/thread (one f32x2 pair) -> ~55 regs -> 3 CTAs/SM
// = 6 warps/SMSP for latency cover; item = 512 atoms -> items/worker = 5.6
// -> tail ~7% (vs 19% at 4 atoms/thread). Channel-major item order keeps
// table reloads at ~1-2 per CTA.
// Horner form:  out = sum_y f_y * ( c0_y + sum_{x<=y} f_x * S_xy )
//               S_xy = c1s_xy + sum_i At_xyi f_i
// ---------------------------------------------------------------------------
__global__ __launch_bounds__(256, 3)
void contract_kernel(const float* __restrict__ feats,
                     float* __restrict__ out,
                     int Natoms, int nItems, int nTiles) {
    const int tid = threadIdx.x;

    __shared__ __align__(16) ull sTab[TAB_ULL];   // 8320 B packed dup'd tables

    // Static contiguous partition of [0, nItems)
    const int g = gridDim.x;
    const int q = nItems / g, r = nItems % g;
    const int b = blockIdx.x;
    int start, cnt;
    if (b < r) { cnt = q + 1; start = b * (q + 1); }
    else       { cnt = q;     start = r * (q + 1) + (b - r) * q; }

    const ull* sA  = sTab;
    const ull* sC1 = sTab + RUN_TOTAL;
    const ull* sC0 = sTab + RUN_TOTAL + NPAIR;

    int curC = -1;
    for (int it = 0; it < cnt; it++) {
        const int id   = start + it;
        const int c    = id / nTiles;          // channel-major ordering
        const int tile = id - c * nTiles;

        if (c != curC) {
            __syncthreads();                   // prior readers of sTab done
            const ulonglong2* src = (const ulonglong2*)(g_tab + (size_t)c * TAB_ULL);
            ulonglong2* dst = (ulonglong2*)sTab;
            for (int j = tid; j < TAB_ULL / 2; j += 256) dst[j] = src[j];
            __syncthreads();
            curC = c;
        }

        const int base = tile * TILE_ATOMS + tid;
        const int n0 = base, n1 = base + 256;
        const bool v0 = n0 < Natoms, v1 = n1 < Natoms;

        float4 fa[4], fb[4];
        {
            const float4* p0 = (const float4*)(feats + ((size_t)n0 * CCH + c) * NI);
            const float4* p1 = (const float4*)(feats + ((size_t)n1 * CCH + c) * NI);
            #pragma unroll
            for (int t = 0; t < 4; t++) {
                fa[t] = v0 ? p0[t] : make_float4(0.f, 0.f, 0.f, 0.f);
                fb[t] = v1 ? p1[t] : make_float4(0.f, 0.f, 0.f, 0.f);
            }
        }
        ull fp[NI];
        #pragma unroll
        for (int t = 0; t < 4; t++) {
            fp[4 * t + 0] = pack2(fa[t].x, fb[t].x);
            fp[4 * t + 1] = pack2(fa[t].y, fb[t].y);
            fp[4 * t + 2] = pack2(fa[t].z, fb[t].z);
            fp[4 * t + 3] = pack2(fa[t].w, fb[t].w);
        }

        ull acc = pack2(0.f, 0.f);

        int roff = 0, pp = 0;
        #pragma unroll
        for (int y = 0; y < NI; y++) {
            const int L  = NI - y;
            const int Lp = (L + 1) & ~1;
            const int i0 = NI - Lp;
            ull t0 = sC0[y];                  // c0 folded into t_y seed
            #pragma unroll
            for (int x = 0; x <= y; x++) {
                ull s = sC1[pp];
                const ulonglong2* rr = (const ulonglong2*)(sA + roff);
                #pragma unroll
                for (int t = 0; t < Lp / 2; t++) {
                    ulonglong2 pv = rr[t];
                    s = fma2(pv.x, fp[i0 + 2 * t + 0], s);
                    s = fma2(pv.y, fp[i0 + 2 * t + 1], s);
                }
                t0 = fma2(s, fp[x], t0);      // t_y += S * f_x
                roff += Lp; pp++;
            }
            acc = fma2(t0, fp[y], acc);       // out += t_y * f_y
        }

        float r0, r1;
        unpack2(acc, r0, r1);
        if (v0) out[(size_t)n0 * CCH + c] = r0;
        if (v1) out[(size_t)n1 * CCH + c] = r1;
    }
}

extern "C" void kernel_launch(void* const* d_in, const int* in_sizes, int n_in,
                              void* d_out, int out_size) {
    const float* feats = (const float*)d_in[0];  // [N, C, I]
    const float* U2    = (const float*)d_in[1];  // [I, I, I, K2]
    const float* U1    = (const float*)d_in[2];  // [I, I, K1]
    const float* U0    = (const float*)d_in[3];  // [I, K0]
    const float* w2    = (const float*)d_in[4];  // [K2, C]
    const float* w1    = (const float*)d_in[5];  // [K1, C]
    const float* w0    = (const float*)d_in[6];  // [K0, C]
    float* out = (float*)d_out;                  // [N, C]

    const int Natoms = in_sizes[0] / (CCH * NI);
    const int nTiles = (Natoms + TILE_ATOMS - 1) / TILE_ATOMS;
    const int nItems = nTiles * CCH;

    prep_kernel<<<57, 256>>>(U2, U1, U0, w2, w1, w0);

    contract_kernel<<<456, 256>>>(feats, out, Natoms, nItems, nTiles);
}

// round 16
// speedup vs baseline: 1.0703x; 1.0703x over previous
#include <cuda_runtime.h>
#include <cstdint>

// Problem constants
#define CCH 64      // channels
#define NI  16      // irreps
#define NK2 120
#define NK1 8
#define NK0 4

#define NPAIR 136        // #(x<=y) pairs
#define RUN_TOTAL 888    // sum over pairs of padded run lengths Lp(y)=((16-y)+1)&~1
#define TAB_ULL   (RUN_TOTAL + NPAIR + NI)   // 1040 ull per channel
#define TILE_ATOMS 512   // atoms per work item (2 per thread, 256 threads)

typedef unsigned long long ull;

// Scratch (__device__ globals; no allocation)
__device__ float g_Usym[RUN_TOTAL * NK2];   // symmetrized U2, padded runs
__device__ float g_U1s[NPAIR * NK1];        // symmetrized U1
__device__ ull   g_tab[CCH * TAB_ULL];      // per-channel packed dup'd tables:
                                            //   [0,888)     At (cubic, padded runs)
                                            //   [888,1024)  c1s
                                            //   [1024,1040) c0s

__device__ __forceinline__ ull pack2(float lo, float hi) {
    ull r; asm("mov.b64 %0,{%1,%2};" : "=l"(r) : "f"(lo), "f"(hi)); return r;
}
__device__ __forceinline__ ull dup2(float v) { return pack2(v, v); }
__device__ __forceinline__ void unpack2(ull v, float& lo, float& hi) {
    asm("mov.b64 {%0,%1},%2;" : "=f"(lo), "=f"(hi) : "l"(v));
}
__device__ __forceinline__ ull fma2(ull a, ull b, ull c) {
    ull d; asm("fma.rn.f32x2 %0,%1,%2,%3;" : "=l"(d) : "l"(a), "l"(b), "l"(c)); return d;
}

// Sum of U2 over DISTINCT index-permutations of the multiset {x,y,i}, at basis k.
__device__ __forceinline__ float sym_sum_U2(const float* __restrict__ U2,
                                            int x, int y, int i, int k) {
    int ta[6] = {x, x, y, y, i, i};
    int tb[6] = {y, i, x, i, x, y};
    int tc[6] = {i, y, i, x, y, x};
    int seen[6]; int ns = 0;
    float v = 0.f;
    #pragma unroll
    for (int q = 0; q < 6; q++) {
        int code = (ta[q] << 8) | (tb[q] << 4) | tc[q];
        bool dup = false;
        for (int s = 0; s < ns; s++) if (seen[s] == code) dup = true;
        if (!dup) {
            seen[ns++] = code;
            v += U2[(((ta[q] * NI + tb[q]) * NI) + tc[q]) * NK2 + k];
        }
    }
    return v;
}

// ---------------------------------------------------------------------------
// Kernel A: symmetrize U2 and U1 — one thread per OUTPUT element.
// ---------------------------------------------------------------------------
__global__ __launch_bounds__(256)
void sym_kernel(const float* __restrict__ U2,
                const float* __restrict__ U1) {
    const int idx = blockIdx.x * 256 + threadIdx.x;
    if (idx < RUN_TOTAL * NK2) {
        const int row = idx / NK2;
        const int k   = idx % NK2;
        int y = 0, base = 0, Lp = 0;
        for (;;) {
            Lp = ((NI - y) + 1) & ~1;
            int sz = (y + 1) * Lp;
            if (row < base + sz) break;
            base += sz; y++;
        }
        int rem = row - base;
        int x = rem / Lp;
        int j = rem - x * Lp;
        int i = (NI - Lp) + j;
        float v = (i >= y) ? sym_sum_U2(U2, x, y, i, k) : 0.f;
        g_Usym[row * NK2 + k] = v;
    } else {
        int idx2 = idx - RUN_TOTAL * NK2;
        if (idx2 < NPAIR * NK1) {
            int p = idx2 / NK1, k = idx2 - (idx2 / NK1) * NK1;
            int y = 0;
            while ((y + 1) * (y + 2) / 2 <= p) y++;
            int x = p - y * (y + 1) / 2;
            float v = U1[(x * NI + y) * NK1 + k];
            if (x != y) v += U1[(y * NI + x) * NK1 + k];
            g_U1s[idx2] = v;
        }
    }
}

// ---------------------------------------------------------------------------
// Kernel B: g_tab[c] = packed dup'd tables (At via smem GEMM; c1s/c0s tiny).
// ---------------------------------------------------------------------------
__global__ __launch_bounds__(256)
void gemm_kernel(const float* __restrict__ w2,
                 const float* __restrict__ w1,
                 const float* __restrict__ w0,
                 const float* __restrict__ U0) {
    const int bid = blockIdx.x, tid = threadIdx.x;
    if (bid < 56) {
        __shared__ float sW[NK2 * CCH];      // 30 KB
        __shared__ float sU[16 * NK2];       // 7.5 KB
        const int r0 = bid * 16;
        for (int i = tid; i < NK2 * CCH; i += 256) sW[i] = w2[i];
        for (int i = tid; i < 16 * NK2; i += 256) {
            int rr = r0 + i / NK2;
            sU[i] = (rr < RUN_TOTAL) ? g_Usym[rr * NK2 + (i % NK2)] : 0.f;
        }
        __syncthreads();
        const int c = tid & 63;
        const int tr = tid >> 6;             // 0..3
        float acc[4] = {0.f, 0.f, 0.f, 0.f};
        #pragma unroll 4
        for (int k = 0; k < NK2; k++) {
            float wv = sW[k * CCH + c];
            #pragma unroll
            for (int q = 0; q < 4; q++)
                acc[q] += sU[(tr + 4 * q) * NK2 + k] * wv;
        }
        #pragma unroll
        for (int q = 0; q < 4; q++) {
            int row = r0 + tr + 4 * q;
            if (row < RUN_TOTAL) g_tab[(size_t)c * TAB_ULL + row] = dup2(acc[q]);
        }
    } else {
        for (int idx = tid; idx < CCH * NPAIR; idx += 256) {
            int c = idx & 63, p = idx >> 6;
            float s = 0.f;
            #pragma unroll
            for (int k = 0; k < NK1; k++) s += g_U1s[p * NK1 + k] * w1[k * CCH + c];
            g_tab[(size_t)c * TAB_ULL + RUN_TOTAL + p] = dup2(s);
        }
        for (int idx = tid; idx < CCH * NI; idx += 256) {
            int c = idx & 63, x = idx >> 6;
            float s = 0.f;
            #pragma unroll
            for (int k = 0; k < NK0; k++) s += U0[x * NK0 + k] * w0[k * CCH + c];
            g_tab[(size_t)c * TAB_ULL + RUN_TOTAL + NPAIR + x] = dup2(s);
        }
    }
}

// ---------------------------------------------------------------------------
// Contract kernel: STATIC channel-major chunking, 456 CTAs (152 SM x 3),
// 256 threads, TWO atoms/thread (one f32x2 pair), 6 warps/SMSP.
// Odd-length runs (y odd) carry a stored leading zero for alignment; we skip
// it: head entry via 8B LDS at roff+1 (i=y), then aligned LDS.128 tail from
// roff+2 — deletes 72 pad fma2 per item (6.9% of fp work) at zero layout risk.
// Horner form:  out = sum_y f_y * ( c0_y + sum_{x<=y} f_x * S_xy )
//               S_xy = c1s_xy + sum_i At_xyi f_i
// ---------------------------------------------------------------------------
__global__ __launch_bounds__(256, 3)
void contract_kernel(const float* __restrict__ feats,
                     float* __restrict__ out,
                     int Natoms, int nItems, int nTiles) {
    const int tid = threadIdx.x;

    __shared__ __align__(16) ull sTab[TAB_ULL];   // 8320 B packed dup'd tables

    // Static contiguous partition of [0, nItems)
    const int g = gridDim.x;
    const int q = nItems / g, r = nItems % g;
    const int b = blockIdx.x;
    int start, cnt;
    if (b < r) { cnt = q + 1; start = b * (q + 1); }
    else       { cnt = q;     start = r * (q + 1) + (b - r) * q; }

    const ull* sA  = sTab;
    const ull* sC1 = sTab + RUN_TOTAL;
    const ull* sC0 = sTab + RUN_TOTAL + NPAIR;

    int curC = -1;
    for (int it = 0; it < cnt; it++) {
        const int id   = start + it;
        const int c    = id / nTiles;          // channel-major ordering
        const int tile = id - c * nTiles;

        if (c != curC) {
            __syncthreads();                   // prior readers of sTab done
            const ulonglong2* src = (const ulonglong2*)(g_tab + (size_t)c * TAB_ULL);
            ulonglong2* dst = (ulonglong2*)sTab;
            for (int j = tid; j < TAB_ULL / 2; j += 256) dst[j] = src[j];
            __syncthreads();
            curC = c;
        }

        const int base = tile * TILE_ATOMS + tid;
        const int n0 = base, n1 = base + 256;
        const bool v0 = n0 < Natoms, v1 = n1 < Natoms;

        float4 fa[4], fb[4];
        {
            const float4* p0 = (const float4*)(feats + ((size_t)n0 * CCH + c) * NI);
            const float4* p1 = (const float4*)(feats + ((size_t)n1 * CCH + c) * NI);
            #pragma unroll
            for (int t = 0; t < 4; t++) {
                fa[t] = v0 ? p0[t] : make_float4(0.f, 0.f, 0.f, 0.f);
                fb[t] = v1 ? p1[t] : make_float4(0.f, 0.f, 0.f, 0.f);
            }
        }
        ull fp[NI];
        #pragma unroll
        for (int t = 0; t < 4; t++) {
            fp[4 * t + 0] = pack2(fa[t].x, fb[t].x);
            fp[4 * t + 1] = pack2(fa[t].y, fb[t].y);
            fp[4 * t + 2] = pack2(fa[t].z, fb[t].z);
            fp[4 * t + 3] = pack2(fa[t].w, fb[t].w);
        }

        ull acc = pack2(0.f, 0.f);

        int roff = 0, pp = 0;
        #pragma unroll
        for (int y = 0; y < NI; y++) {
            const int L  = NI - y;
            const int Lp = (L + 1) & ~1;
            ull t0 = sC0[y];                  // c0 folded into t_y seed
            #pragma unroll
            for (int x = 0; x <= y; x++) {
                ull s = sC1[pp];
                if (L & 1) {
                    // pad at roff (zero, i=y-1) — skip it entirely.
                    ull h = sA[roff + 1];     // 8B LDS, i = y
                    s = fma2(h, fp[y], s);
                    const ulonglong2* rr = (const ulonglong2*)(sA + roff + 2);
                    #pragma unroll
                    for (int t = 0; t < (L - 1) / 2; t++) {
                        ulonglong2 pv = rr[t];
                        s = fma2(pv.x, fp[y + 1 + 2 * t], s);
                        s = fma2(pv.y, fp[y + 2 + 2 * t], s);
                    }
                } else {
                    const ulonglong2* rr = (const ulonglong2*)(sA + roff);
                    #pragma unroll
                    for (int t = 0; t < L / 2; t++) {
                        ulonglong2 pv = rr[t];
                        s = fma2(pv.x, fp[y + 2 * t], s);
                        s = fma2(pv.y, fp[y + 1 + 2 * t], s);
                    }
                }
                t0 = fma2(s, fp[x], t0);      // t_y += S * f_x
                roff += Lp; pp++;
            }
            acc = fma2(t0, fp[y], acc);       // out += t_y * f_y
        }

        float r0, r1;
        unpack2(acc, r0, r1);
        if (v0) out[(size_t)n0 * CCH + c] = r0;
        if (v1) out[(size_t)n1 * CCH + c] = r1;
    }
}

extern "C" void kernel_launch(void* const* d_in, const int* in_sizes, int n_in,
                              void* d_out, int out_size) {
    const float* feats = (const float*)d_in[0];  // [N, C, I]
    const float* U2    = (const float*)d_in[1];  // [I, I, I, K2]
    const float* U1    = (const float*)d_in[2];  // [I, I, K1]
    const float* U0    = (const float*)d_in[3];  // [I, K0]
    const float* w2    = (const float*)d_in[4];  // [K2, C]
    const float* w1    = (const float*)d_in[5];  // [K1, C]
    const float* w0    = (const float*)d_in[6];  // [K0, C]
    float* out = (float*)d_out;                  // [N, C]

    const int Natoms = in_sizes[0] / (CCH * NI);
    const int nTiles = (Natoms + TILE_ATOMS - 1) / TILE_ATOMS;
    const int nItems = nTiles * CCH;

    const int symElems = RUN_TOTAL * NK2 + NPAIR * NK1;
    sym_kernel<<<(symElems + 255) / 256, 256>>>(U2, U1);
    gemm_kernel<<<57, 256>>>(w2, w1, w0, U0);

    contract_kernel<<<456, 256>>>(feats, out, Natoms, nItems, nTiles);
}